// round 6
// baseline (speedup 1.0000x reference)
#include <cuda_runtime.h>
#include <cstdint>

// ---------------------------------------------------------------------------
// Modified MHA (no input proj) + dual output projections. TF32 tensor cores.
// Round 6: pre-converted fragment-native gmem layouts, zero smem, zero staging,
//          in-register C-frag -> A-frag shuffle for P and for attn epilogue.
// ---------------------------------------------------------------------------

#define BB 16
#define LL 1024
#define SS 1024
#define EE 512
#define HH 8
#define HD 64

// ---- fragment-layout gmem scratch ------------------------------------------
// A-frag: frag F holds 16x8 tile; float addr = F*128 + lane*4 + {a0,a1,a2,a3}
//   a0=A[g][t] a1=A[g+8][t] a2=A[g][t+4] a3=A[g+8][t+4]   (g=lane>>2,t=lane&3)
// B-frag: frag holds 8(k)x8(n); float addr = idx*64 + lane*2 + {b0,b1}
//   b0=B[t][g] b1=B[t+4][g]
__device__ float g_qf   [(size_t)1024 * 64 * 128];  // Q  A-frags: F = mf*64 + (h*8+kf)
__device__ float g_kf   [(size_t)128 * 128 * 8 * 64]; // K B-frags: ((bh*128+sf)*8+kf)
__device__ float g_vf   [(size_t)128 * 128 * 8 * 64]; // V B-frags: ((bh*128+skf)*8+dnf)
__device__ float g_attnf[(size_t)1024 * 64 * 128];  // attn A-frags (tf32)
__device__ float g_w1f  [(size_t)64 * 64 * 64];     // W1 B-frags: (nf*64+kf)
__device__ float g_w2f  [(size_t)64 * 64 * 64];

// ---- helpers ----------------------------------------------------------------

__device__ __forceinline__ float f2tf(float x) {
    uint32_t r;
    asm volatile("cvt.rna.tf32.f32 %0, %1;" : "=r"(r) : "f"(x));
    return __uint_as_float(r);
}

__device__ __forceinline__ void mma_tf32(float c[4], float a0, float a1,
                                         float a2, float a3, float b0, float b1) {
    asm volatile(
        "mma.sync.aligned.m16n8k8.row.col.f32.tf32.tf32.f32 "
        "{%0,%1,%2,%3}, {%4,%5,%6,%7}, {%8,%9}, {%0,%1,%2,%3};\n"
        : "+f"(c[0]), "+f"(c[1]), "+f"(c[2]), "+f"(c[3])
        : "r"(__float_as_uint(a0)), "r"(__float_as_uint(a1)),
          "r"(__float_as_uint(a2)), "r"(__float_as_uint(a3)),
          "r"(__float_as_uint(b0)), "r"(__float_as_uint(b1)));
}

// ---- conversion kernels -------------------------------------------------------

// Q (B,L,E) -> A-frags, pre-scaled by hd^-0.5, tf32. 65536 frags.
__global__ void __launch_bounds__(256)
conv_q(const float* __restrict__ q) {
    int idx = blockIdx.x * 256 + threadIdx.x;       // 2,097,152
    int lane = idx & 31, F = idx >> 5;
    int mf = F >> 6, ef = F & 63;
    int g = lane >> 2, t = lane & 3;
    const float* base = q + ((size_t)(mf * 16 + g)) * EE + ef * 8 + t;
    float4 o;
    o.x = f2tf(base[0]        * 0.125f);
    o.y = f2tf(base[8 * EE]   * 0.125f);
    o.z = f2tf(base[4]        * 0.125f);
    o.w = f2tf(base[8 * EE + 4] * 0.125f);
    *reinterpret_cast<float4*>(g_qf + (size_t)F * 128 + lane * 4) = o;
}

// K,V (B,S,E) -> B-frags. 131072 frags each.
__global__ void __launch_bounds__(256)
conv_kv(const float* __restrict__ kmat, const float* __restrict__ vmat) {
    int idx = blockIdx.x * 256 + threadIdx.x;       // 4,194,304
    int lane = idx & 31, F = idx >> 5;
    int bh = F >> 10, sf = (F >> 3) & 127, kf = F & 7;
    int b = bh >> 3, h = bh & 7;
    // K: frag (sf over s, kf over d). b0=K[sb+g][db+t], b1=K[sb+g][db+t+4]
    {
        const float* kb = kmat + ((size_t)b * SS + sf * 8 + (lane >> 2)) * EE
                        + h * HD + kf * 8 + (lane & 3);
        float2 o = make_float2(f2tf(kb[0]), f2tf(kb[4]));
        *reinterpret_cast<float2*>(g_kf + (size_t)F * 64 + lane * 2) = o;
    }
    // V: frag (sf over s(k-dim), kf over d(n-dim)). b0=V[sb+t][db+g], b1=V[sb+t+4][db+g]
    {
        const float* vb = vmat + ((size_t)b * SS + sf * 8 + (lane & 3)) * EE
                        + h * HD + kf * 8 + (lane >> 2);
        float2 o = make_float2(f2tf(vb[0]), f2tf(vb[4 * EE]));
        *reinterpret_cast<float2*>(g_vf + (size_t)F * 64 + lane * 2) = o;
    }
}

// W1,W2 (E,E) row-major, out = attn @ W^T: B-frag k=e_in, n=e_out. 4096 frags each.
__global__ void __launch_bounds__(256)
conv_w(const float* __restrict__ w1, const float* __restrict__ w2) {
    int idx = blockIdx.x * 256 + threadIdx.x;       // 131,072
    int lane = idx & 31, F = idx >> 5;
    int nf = F >> 6, kf = F & 63;
    size_t off = (size_t)(nf * 8 + (lane >> 2)) * EE + kf * 8 + (lane & 3);
    *reinterpret_cast<float2*>(g_w1f + (size_t)F * 64 + lane * 2) =
        make_float2(f2tf(w1[off]), f2tf(w1[off + 4]));
    *reinterpret_cast<float2*>(g_w2f + (size_t)F * 64 + lane * 2) =
        make_float2(f2tf(w2[off]), f2tf(w2[off + 4]));
}

// ---- in-register C-frag -> A-frag shuffle ------------------------------------
// a0=P[g][t] a1=P[g+8][t] a2=P[g][t+4] a3=P[g+8][t+4] from C-frag regs c0..c3.
__device__ __forceinline__ void cfrag_to_afrag(float c[4], int srcA, int srcB, bool odd) {
    float u0 = __shfl_sync(0xffffffffu, c[0], srcA);
    float u1 = __shfl_sync(0xffffffffu, c[1], srcA);
    float u2 = __shfl_sync(0xffffffffu, c[2], srcA);
    float u3 = __shfl_sync(0xffffffffu, c[3], srcA);
    float w0 = __shfl_sync(0xffffffffu, c[0], srcB);
    float w1 = __shfl_sync(0xffffffffu, c[1], srcB);
    float w2 = __shfl_sync(0xffffffffu, c[2], srcB);
    float w3 = __shfl_sync(0xffffffffu, c[3], srcB);
    c[0] = odd ? u1 : u0;   // a0
    c[1] = odd ? u3 : u2;   // a1
    c[2] = odd ? w1 : w0;   // a2
    c[3] = odd ? w3 : w2;   // a3
}

// ---- Kernel 1: flash attention (no smem) -------------------------------------
// Block = 128 thr / 4 warps, m=128 (warp m=32, mi=0,1). STILE=64.

__global__ void __launch_bounds__(128, 3)
attn_kernel() {
    const int tid  = threadIdx.x;
    const int warp = tid >> 5;
    const int lane = tid & 31;
    const int g = lane >> 2, t = lane & 3;
    const int srcA = g * 4 + (t >> 1);
    const int srcB = srcA + 2;
    const bool odd = (t & 1) != 0;

    const int ltile = blockIdx.x;   // 0..7
    const int h     = blockIdx.y;   // 0..7
    const int b     = blockIdx.z;   // 0..15
    const int bh    = b * 8 + h;
    const int mfbase = b * 64 + ltile * 8 + warp * 2;

    const float* qf0 = g_qf + ((size_t)mfbase * 64 + h * 8) * 128 + lane * 4;
    const float* qf1 = qf0 + (size_t)64 * 128;

    float m_prev[2][2] = {{-1e30f, -1e30f}, {-1e30f, -1e30f}};
    float l_sum[2][2]  = {{0.f, 0.f}, {0.f, 0.f}};
    float acc[2][8][4];
    #pragma unroll
    for (int mi = 0; mi < 2; mi++)
        #pragma unroll
        for (int ni = 0; ni < 8; ni++)
            #pragma unroll
            for (int i = 0; i < 4; i++) acc[mi][ni][i] = 0.f;

    for (int st = 0; st < SS; st += 64) {
        const float* kfb = g_kf + (((size_t)bh * 128 + (st >> 3)) * 8) * 64 + lane * 2;
        const float* vfb = g_vf + (((size_t)bh * 128 + (st >> 3)) * 8) * 64 + lane * 2;

        // ---- scores = Q @ K^T ----
        float sc[2][8][4];
        #pragma unroll
        for (int mi = 0; mi < 2; mi++)
            #pragma unroll
            for (int ni = 0; ni < 8; ni++)
                #pragma unroll
                for (int i = 0; i < 4; i++) sc[mi][ni][i] = 0.f;

        #pragma unroll
        for (int ki = 0; ki < 8; ki++) {
            float4 qa0 = __ldg(reinterpret_cast<const float4*>(qf0 + ki * 128));
            float4 qa1 = __ldg(reinterpret_cast<const float4*>(qf1 + ki * 128));
            #pragma unroll
            for (int ni = 0; ni < 8; ni++) {
                float2 bv = __ldg(reinterpret_cast<const float2*>(
                    kfb + (size_t)(ni * 8 + ki) * 64));
                mma_tf32(sc[0][ni], qa0.x, qa0.y, qa0.z, qa0.w, bv.x, bv.y);
                mma_tf32(sc[1][ni], qa1.x, qa1.y, qa1.z, qa1.w, bv.x, bv.y);
            }
        }

        // ---- online softmax (rows g / g+8); P left in sc as tf32 ----
        #pragma unroll
        for (int mi = 0; mi < 2; mi++) {
            float mt0 = -1e30f, mt1 = -1e30f;
            #pragma unroll
            for (int ni = 0; ni < 8; ni++) {
                mt0 = fmaxf(mt0, fmaxf(sc[mi][ni][0], sc[mi][ni][1]));
                mt1 = fmaxf(mt1, fmaxf(sc[mi][ni][2], sc[mi][ni][3]));
            }
            mt0 = fmaxf(mt0, __shfl_xor_sync(0xffffffffu, mt0, 1));
            mt0 = fmaxf(mt0, __shfl_xor_sync(0xffffffffu, mt0, 2));
            mt1 = fmaxf(mt1, __shfl_xor_sync(0xffffffffu, mt1, 1));
            mt1 = fmaxf(mt1, __shfl_xor_sync(0xffffffffu, mt1, 2));
            float mn0 = fmaxf(m_prev[mi][0], mt0);
            float mn1 = fmaxf(m_prev[mi][1], mt1);
            float al0 = __expf(m_prev[mi][0] - mn0);
            float al1 = __expf(m_prev[mi][1] - mn1);
            m_prev[mi][0] = mn0; m_prev[mi][1] = mn1;

            float rs0 = 0.f, rs1 = 0.f;
            #pragma unroll
            for (int ni = 0; ni < 8; ni++) {
                float p0 = __expf(sc[mi][ni][0] - mn0);
                float p1 = __expf(sc[mi][ni][1] - mn0);
                float p2 = __expf(sc[mi][ni][2] - mn1);
                float p3 = __expf(sc[mi][ni][3] - mn1);
                rs0 += p0 + p1; rs1 += p2 + p3;
                sc[mi][ni][0] = f2tf(p0); sc[mi][ni][1] = f2tf(p1);
                sc[mi][ni][2] = f2tf(p2); sc[mi][ni][3] = f2tf(p3);
            }
            rs0 += __shfl_xor_sync(0xffffffffu, rs0, 1);
            rs0 += __shfl_xor_sync(0xffffffffu, rs0, 2);
            rs1 += __shfl_xor_sync(0xffffffffu, rs1, 1);
            rs1 += __shfl_xor_sync(0xffffffffu, rs1, 2);
            l_sum[mi][0] = l_sum[mi][0] * al0 + rs0;
            l_sum[mi][1] = l_sum[mi][1] * al1 + rs1;
            #pragma unroll
            for (int ni = 0; ni < 8; ni++) {
                acc[mi][ni][0] *= al0; acc[mi][ni][1] *= al0;
                acc[mi][ni][2] *= al1; acc[mi][ni][3] *= al1;
            }
            // C-frag -> A-frag in place (P fragment for PV, k-frag = ni)
            #pragma unroll
            for (int ni = 0; ni < 8; ni++)
                cfrag_to_afrag(sc[mi][ni], srcA, srcB, odd);
        }

        // ---- acc += P @ V ----
        #pragma unroll
        for (int j = 0; j < 8; j++) {          // k-frags over s
            #pragma unroll
            for (int nd = 0; nd < 8; nd++) {   // n-frags over d
                float2 bv = __ldg(reinterpret_cast<const float2*>(
                    vfb + (size_t)(j * 8 + nd) * 64));
                mma_tf32(acc[0][nd], sc[0][j][0], sc[0][j][1], sc[0][j][2], sc[0][j][3],
                         bv.x, bv.y);
                mma_tf32(acc[1][nd], sc[1][j][0], sc[1][j][1], sc[1][j][2], sc[1][j][3],
                         bv.x, bv.y);
            }
        }
    }

    // ---- epilogue: normalize, tf32, shuffle to A-frag, store to g_attnf ----
    #pragma unroll
    for (int mi = 0; mi < 2; mi++) {
        float inv0 = 1.f / l_sum[mi][0];
        float inv1 = 1.f / l_sum[mi][1];
        float* ob = g_attnf + ((size_t)(mfbase + mi) * 64 + h * 8) * 128 + lane * 4;
        #pragma unroll
        for (int nd = 0; nd < 8; nd++) {
            float c[4];
            c[0] = f2tf(acc[mi][nd][0] * inv0);
            c[1] = f2tf(acc[mi][nd][1] * inv0);
            c[2] = f2tf(acc[mi][nd][2] * inv1);
            c[3] = f2tf(acc[mi][nd][3] * inv1);
            cfrag_to_afrag(c, srcA, srcB, odd);
            *reinterpret_cast<float4*>(ob + (size_t)nd * 128) =
                make_float4(c[0], c[1], c[2], c[3]);
        }
    }
}

// ---- Kernel 2: dual output projection (no smem) --------------------------------
// Block = 128 thr / 4 warps, tile m=128 (warp m=32) x n=64, both mats.

__global__ void __launch_bounds__(128, 3)
proj_kernel(const float* __restrict__ bias1, const float* __restrict__ bias2,
            float* __restrict__ out)
{
    const int tid  = threadIdx.x;
    const int warp = tid >> 5;
    const int lane = tid & 31;
    const int g = lane >> 2, t = lane & 3;

    const int mt = blockIdx.x;   // 0..127
    const int nt = blockIdx.y;   // 0..7
    const int mfb = mt * 8 + warp * 2;

    const float* af0 = g_attnf + (size_t)mfb * 64 * 128 + lane * 4;
    const float* af1 = af0 + (size_t)64 * 128;
    const float* w1b = g_w1f + (size_t)nt * 8 * 64 * 64 + lane * 2;
    const float* w2b = g_w2f + (size_t)nt * 8 * 64 * 64 + lane * 2;

    float acc1[2][8][4], acc2[2][8][4];
    #pragma unroll
    for (int mi = 0; mi < 2; mi++)
        #pragma unroll
        for (int ni = 0; ni < 8; ni++)
            #pragma unroll
            for (int i = 0; i < 4; i++) { acc1[mi][ni][i] = 0.f; acc2[mi][ni][i] = 0.f; }

    for (int kc = 0; kc < 8; kc++) {
        #pragma unroll
        for (int ki = 0; ki < 8; ki++) {
            int kf = kc * 8 + ki;
            float4 a0 = __ldg(reinterpret_cast<const float4*>(af0 + (size_t)kf * 128));
            float4 a1 = __ldg(reinterpret_cast<const float4*>(af1 + (size_t)kf * 128));
            #pragma unroll
            for (int ni = 0; ni < 8; ni++) {
                float2 b1 = __ldg(reinterpret_cast<const float2*>(
                    w1b + (size_t)(ni * 64 + kf) * 64));
                mma_tf32(acc1[0][ni], a0.x, a0.y, a0.z, a0.w, b1.x, b1.y);
                mma_tf32(acc1[1][ni], a1.x, a1.y, a1.z, a1.w, b1.x, b1.y);
                float2 b2 = __ldg(reinterpret_cast<const float2*>(
                    w2b + (size_t)(ni * 64 + kf) * 64));
                mma_tf32(acc2[0][ni], a0.x, a0.y, a0.z, a0.w, b2.x, b2.y);
                mma_tf32(acc2[1][ni], a1.x, a1.y, a1.z, a1.w, b2.x, b2.y);
            }
        }
    }

    // ---- epilogue: bias + store (C-frag layout straight to gmem) ----
    const size_t obase = ((size_t)mt * 128 + warp * 32) * EE + (size_t)nt * 64;
    float* o1 = out + obase;
    float* o2 = out + (size_t)BB * LL * EE + obase;
    #pragma unroll
    for (int ni = 0; ni < 8; ni++) {
        int col = ni * 8 + 2 * t;
        float ba1 = __ldg(bias1 + nt * 64 + col);
        float bb1 = __ldg(bias1 + nt * 64 + col + 1);
        float ba2 = __ldg(bias2 + nt * 64 + col);
        float bb2 = __ldg(bias2 + nt * 64 + col + 1);
        #pragma unroll
        for (int mi = 0; mi < 2; mi++) {
            size_t roff = (size_t)(mi * 16) * EE;
            *reinterpret_cast<float2*>(o1 + roff + (size_t)g * EE + col) =
                make_float2(acc1[mi][ni][0] + ba1, acc1[mi][ni][1] + bb1);
            *reinterpret_cast<float2*>(o1 + roff + (size_t)(g + 8) * EE + col) =
                make_float2(acc1[mi][ni][2] + ba1, acc1[mi][ni][3] + bb1);
            *reinterpret_cast<float2*>(o2 + roff + (size_t)g * EE + col) =
                make_float2(acc2[mi][ni][0] + ba2, acc2[mi][ni][1] + bb2);
            *reinterpret_cast<float2*>(o2 + roff + (size_t)(g + 8) * EE + col) =
                make_float2(acc2[mi][ni][2] + ba2, acc2[mi][ni][3] + bb2);
        }
    }
}

// ---- launch -------------------------------------------------------------------

extern "C" void kernel_launch(void* const* d_in, const int* in_sizes, int n_in,
                              void* d_out, int out_size) {
    (void)in_sizes; (void)n_in; (void)out_size;
    const float* q  = (const float*)d_in[0];
    const float* k  = (const float*)d_in[1];
    const float* v  = (const float*)d_in[2];
    const float* w1 = (const float*)d_in[3];
    const float* b1 = (const float*)d_in[4];
    const float* w2 = (const float*)d_in[5];
    const float* b2 = (const float*)d_in[6];
    float* out = (float*)d_out;

    conv_q <<<8192,  256>>>(q);
    conv_kv<<<16384, 256>>>(k, v);
    conv_w <<<512,   256>>>(w1, w2);

    dim3 grid1(LL / 128, HH, BB);   // (8, 8, 16) = 1024 blocks
    attn_kernel<<<grid1, 128>>>();

    dim3 grid2((BB * LL) / 128, EE / 64);  // (128, 8) = 1024 blocks
    proj_kernel<<<grid2, 128>>>(b1, b2, out);
}

// round 7
// speedup vs baseline: 2.7235x; 2.7235x over previous
#include <cuda_runtime.h>
#include <cstdint>

// ---------------------------------------------------------------------------
// Modified MHA (no input proj) + dual output projections. TF32 tensor cores.
// Round 7: cp.async double-buffered smem staging + ldmatrix.x4 fragment loads
//          from XOR-swizzled row-major tiles; Q frags register-resident;
//          V pre-transposed+tf32-rounded once; proj as one N=1024 GEMM.
// ---------------------------------------------------------------------------

#define BB 16
#define LL 1024
#define SS 1024
#define EE 512
#define HH 8
#define HD 64

// scratch
__device__ float g_vt  [(size_t)BB * HH * HD * SS];   // V^T per (b,h): [d][s], tf32
__device__ float g_attn[(size_t)BB * LL * EE];        // attention out (tf32-rounded)

// ---- helpers ----------------------------------------------------------------

__device__ __forceinline__ float f2tf(float x) {
    uint32_t r;
    asm volatile("cvt.rna.tf32.f32 %0, %1;" : "=r"(r) : "f"(x));
    return __uint_as_float(r);
}

__device__ __forceinline__ void mma_tf32(float c[4], const float a[4],
                                         float b0, float b1) {
    asm volatile(
        "mma.sync.aligned.m16n8k8.row.col.f32.tf32.tf32.f32 "
        "{%0,%1,%2,%3}, {%4,%5,%6,%7}, {%8,%9}, {%0,%1,%2,%3};\n"
        : "+f"(c[0]), "+f"(c[1]), "+f"(c[2]), "+f"(c[3])
        : "r"(__float_as_uint(a[0])), "r"(__float_as_uint(a[1])),
          "r"(__float_as_uint(a[2])), "r"(__float_as_uint(a[3])),
          "r"(__float_as_uint(b0)), "r"(__float_as_uint(b1)));
}

__device__ __forceinline__ void ldsm4(uint32_t& d0, uint32_t& d1,
                                      uint32_t& d2, uint32_t& d3, uint32_t a) {
    asm volatile("ldmatrix.sync.aligned.m8n8.x4.shared.b16 {%0,%1,%2,%3}, [%4];"
                 : "=r"(d0), "=r"(d1), "=r"(d2), "=r"(d3) : "r"(a));
}

__device__ __forceinline__ void cp16(uint32_t s, const void* g) {
    asm volatile("cp.async.ca.shared.global [%0], [%1], 16;" :: "r"(s), "l"(g));
}
__device__ __forceinline__ void cp_commit() {
    asm volatile("cp.async.commit_group;");
}
template <int N>
__device__ __forceinline__ void cp_wait() {
    asm volatile("cp.async.wait_group %0;" :: "n"(N));
}

// in-register C-frag -> A-frag (verified in round 6)
__device__ __forceinline__ void cfrag_to_afrag(float c[4], int srcA, int srcB, bool odd) {
    float u0 = __shfl_sync(0xffffffffu, c[0], srcA);
    float u1 = __shfl_sync(0xffffffffu, c[1], srcA);
    float u2 = __shfl_sync(0xffffffffu, c[2], srcA);
    float u3 = __shfl_sync(0xffffffffu, c[3], srcA);
    float w0 = __shfl_sync(0xffffffffu, c[0], srcB);
    float w1 = __shfl_sync(0xffffffffu, c[1], srcB);
    float w2 = __shfl_sync(0xffffffffu, c[2], srcB);
    float w3 = __shfl_sync(0xffffffffu, c[3], srcB);
    c[0] = odd ? u1 : u0;
    c[1] = odd ? u3 : u2;
    c[2] = odd ? w1 : w0;
    c[3] = odd ? w3 : w2;
}

// ---- conv_v: transpose V head-slices + tf32 round ----------------------------
__global__ void __launch_bounds__(256)
conv_v(const float* __restrict__ v) {
    __shared__ float tsm[64][65];
    const int stile = blockIdx.x;     // 0..15
    const int bh    = blockIdx.y;     // 0..127
    const int b = bh >> 3, h = bh & 7;
    const float* vg = v + ((size_t)b * SS + stile * 64) * EE + h * HD;
    for (int i = threadIdx.x; i < 1024; i += 256) {
        int r = i >> 4, c4 = (i & 15) * 4;
        float4 x = *reinterpret_cast<const float4*>(vg + (size_t)r * EE + c4);
        tsm[r][c4]     = f2tf(x.x);
        tsm[r][c4 + 1] = f2tf(x.y);
        tsm[r][c4 + 2] = f2tf(x.z);
        tsm[r][c4 + 3] = f2tf(x.w);
    }
    __syncthreads();
    float* og = g_vt + (size_t)bh * HD * SS + stile * 64;
    for (int i = threadIdx.x; i < 1024; i += 256) {
        int d = i >> 4, s4 = (i & 15) * 4;
        float4 y = make_float4(tsm[s4][d], tsm[s4 + 1][d], tsm[s4 + 2][d], tsm[s4 + 3][d]);
        *reinterpret_cast<float4*>(og + (size_t)d * SS + s4) = y;
    }
}

// ---- Kernel 1: flash attention ------------------------------------------------
// 128 thr / 4 warps, 128 q-rows per block (warp m=32), STILE=64, double-buffered.
// smem floats: sQ 128x64 @0 ; sK[2] 64x64 @8192 ; sV[2] 64x64 @16384
#define ATTN_SMEM (24576 * 4)

__global__ void __launch_bounds__(128, 2)
attn_kernel(const float* __restrict__ q, const float* __restrict__ kmat)
{
    extern __shared__ float smem[];
    const uint32_t sb  = (uint32_t)__cvta_generic_to_shared(smem);
    const uint32_t sQ  = sb;
    const uint32_t sK0 = sb + 8192 * 4;
    const uint32_t sV0 = sb + 16384 * 4;

    const int tid  = threadIdx.x;
    const int warp = tid >> 5;
    const int lane = tid & 31;
    const int g = lane >> 2, t = lane & 3;
    const int srcA = g * 4 + (t >> 1);
    const int srcB = srcA + 2;
    const bool odd = (t & 1) != 0;
    const int lxor = lane & 7;
    // ldmatrix address components
    const int aRow = lane & 15, aSel = lane >> 4;            // A pattern
    const int bRow = ((lane >> 4) << 3) + (lane & 7);        // B pattern
    const int bSel = (lane >> 3) & 1;

    const int ltile = blockIdx.x;   // 0..7
    const int h     = blockIdx.y;   // 0..7
    const int b     = blockIdx.z;   // 0..15
    const int bh    = b * 8 + h;

    const float* qg = q + ((size_t)b * LL + (size_t)ltile * 128) * EE + h * HD;
    const float* kg = kmat + (size_t)b * SS * EE + h * HD;
    const float* vg = g_vt + (size_t)bh * HD * SS;

    // ---- stage Q (128x64) + first K/V tile, one commit group ----
    #pragma unroll
    for (int j = 0; j < 16; j++) {
        int i = tid + j * 128;
        int r = i >> 4, c = i & 15;
        cp16(sQ + (r << 8) + (((c ^ (r & 7)) << 4)), qg + (size_t)r * EE + c * 4);
    }
    #pragma unroll
    for (int j = 0; j < 8; j++) {
        int i = tid + j * 128;
        int r = i >> 4, c = i & 15;
        uint32_t soff = (r << 8) + ((c ^ (r & 7)) << 4);
        cp16(sK0 + soff, kg + (size_t)r * EE + c * 4);
        cp16(sV0 + soff, vg + (size_t)r * SS + c * 4);
    }
    cp_commit();

    float qf[2][8][4];
    float m_prev[2][2] = {{-1e30f, -1e30f}, {-1e30f, -1e30f}};
    float l_sum[2][2]  = {{0.f, 0.f}, {0.f, 0.f}};
    float acc[2][8][4];
    #pragma unroll
    for (int mi = 0; mi < 2; mi++)
        #pragma unroll
        for (int ni = 0; ni < 8; ni++)
            #pragma unroll
            for (int i = 0; i < 4; i++) acc[mi][ni][i] = 0.f;

    const float SOFT = 0.125f * 1.4426950408889634f;  // hd^-0.5 * log2(e)

    #pragma unroll 1
    for (int tt = 0; tt < 16; tt++) {
        const uint32_t sKb = sK0 + (tt & 1) * 4096 * 4;
        const uint32_t sVb = sV0 + (tt & 1) * 4096 * 4;

        // prefetch next K/V tile into other buffer
        if (tt + 1 < 16) {
            const uint32_t sKn = sK0 + ((tt + 1) & 1) * 4096 * 4;
            const uint32_t sVn = sV0 + ((tt + 1) & 1) * 4096 * 4;
            const float* kgn = kg + (size_t)(tt + 1) * 64 * EE;
            const float* vgn = vg + (size_t)(tt + 1) * 64;
            #pragma unroll
            for (int j = 0; j < 8; j++) {
                int i = tid + j * 128;
                int r = i >> 4, c = i & 15;
                uint32_t soff = (r << 8) + ((c ^ (r & 7)) << 4);
                cp16(sKn + soff, kgn + (size_t)r * EE + c * 4);
                cp16(sVn + soff, vgn + (size_t)r * SS + c * 4);
            }
            cp_commit();
            cp_wait<1>();
        } else {
            cp_wait<0>();
        }
        __syncthreads();

        if (tt == 0) {
            // Q fragments -> registers (raw fp32 -> tf32 rna)
            #pragma unroll
            for (int mi = 0; mi < 2; mi++)
                #pragma unroll
                for (int ki = 0; ki < 8; ki++) {
                    int r = warp * 32 + mi * 16 + aRow;
                    uint32_t addr = sQ + (r << 8) + ((((2 * ki + aSel)) ^ lxor) << 4);
                    uint32_t u0, u1, u2, u3;
                    ldsm4(u0, u1, u2, u3, addr);
                    qf[mi][ki][0] = f2tf(__uint_as_float(u0));
                    qf[mi][ki][1] = f2tf(__uint_as_float(u1));
                    qf[mi][ki][2] = f2tf(__uint_as_float(u2));
                    qf[mi][ki][3] = f2tf(__uint_as_float(u3));
                }
        }

        // ---- scores = Q @ K^T ----
        float sc[2][8][4];
        #pragma unroll
        for (int mi = 0; mi < 2; mi++)
            #pragma unroll
            for (int ni = 0; ni < 8; ni++)
                #pragma unroll
                for (int i = 0; i < 4; i++) sc[mi][ni][i] = 0.f;

        #pragma unroll
        for (int ki = 0; ki < 8; ki++) {
            #pragma unroll
            for (int nip = 0; nip < 4; nip++) {
                uint32_t u0, u1, u2, u3;
                uint32_t addr = sKb + ((nip * 16 + bRow) << 8)
                              + (((2 * ki + bSel) ^ lxor) << 4);
                ldsm4(u0, u1, u2, u3, addr);
                float k0 = f2tf(__uint_as_float(u0));
                float k1 = f2tf(__uint_as_float(u1));
                float k2 = f2tf(__uint_as_float(u2));
                float k3 = f2tf(__uint_as_float(u3));
                mma_tf32(sc[0][2 * nip],     qf[0][ki], k0, k1);
                mma_tf32(sc[1][2 * nip],     qf[1][ki], k0, k1);
                mma_tf32(sc[0][2 * nip + 1], qf[0][ki], k2, k3);
                mma_tf32(sc[1][2 * nip + 1], qf[1][ki], k2, k3);
            }
        }

        // ---- online softmax (scale folded into exp2 constant) ----
        #pragma unroll
        for (int mi = 0; mi < 2; mi++) {
            float mt0 = -1e30f, mt1 = -1e30f;
            #pragma unroll
            for (int ni = 0; ni < 8; ni++) {
                mt0 = fmaxf(mt0, fmaxf(sc[mi][ni][0], sc[mi][ni][1]));
                mt1 = fmaxf(mt1, fmaxf(sc[mi][ni][2], sc[mi][ni][3]));
            }
            mt0 = fmaxf(mt0, __shfl_xor_sync(0xffffffffu, mt0, 1));
            mt0 = fmaxf(mt0, __shfl_xor_sync(0xffffffffu, mt0, 2));
            mt1 = fmaxf(mt1, __shfl_xor_sync(0xffffffffu, mt1, 1));
            mt1 = fmaxf(mt1, __shfl_xor_sync(0xffffffffu, mt1, 2));
            float mn0 = fmaxf(m_prev[mi][0], mt0);
            float mn1 = fmaxf(m_prev[mi][1], mt1);
            float al0 = exp2f((m_prev[mi][0] - mn0) * SOFT);
            float al1 = exp2f((m_prev[mi][1] - mn1) * SOFT);
            m_prev[mi][0] = mn0; m_prev[mi][1] = mn1;

            float rs0 = 0.f, rs1 = 0.f;
            #pragma unroll
            for (int ni = 0; ni < 8; ni++) {
                float p0 = exp2f((sc[mi][ni][0] - mn0) * SOFT);
                float p1 = exp2f((sc[mi][ni][1] - mn0) * SOFT);
                float p2 = exp2f((sc[mi][ni][2] - mn1) * SOFT);
                float p3 = exp2f((sc[mi][ni][3] - mn1) * SOFT);
                rs0 += p0 + p1; rs1 += p2 + p3;
                sc[mi][ni][0] = f2tf(p0); sc[mi][ni][1] = f2tf(p1);
                sc[mi][ni][2] = f2tf(p2); sc[mi][ni][3] = f2tf(p3);
            }
            rs0 += __shfl_xor_sync(0xffffffffu, rs0, 1);
            rs0 += __shfl_xor_sync(0xffffffffu, rs0, 2);
            rs1 += __shfl_xor_sync(0xffffffffu, rs1, 1);
            rs1 += __shfl_xor_sync(0xffffffffu, rs1, 2);
            l_sum[mi][0] = l_sum[mi][0] * al0 + rs0;
            l_sum[mi][1] = l_sum[mi][1] * al1 + rs1;
            #pragma unroll
            for (int ni = 0; ni < 8; ni++) {
                acc[mi][ni][0] *= al0; acc[mi][ni][1] *= al0;
                acc[mi][ni][2] *= al1; acc[mi][ni][3] *= al1;
            }
            #pragma unroll
            for (int ni = 0; ni < 8; ni++)
                cfrag_to_afrag(sc[mi][ni], srcA, srcB, odd);
        }

        // ---- acc += P @ V  (V^T tiles: rows=d, cols=s, pre-rounded) ----
        #pragma unroll
        for (int j = 0; j < 8; j++) {
            #pragma unroll
            for (int ndp = 0; ndp < 4; ndp++) {
                uint32_t u0, u1, u2, u3;
                uint32_t addr = sVb + ((ndp * 16 + bRow) << 8)
                              + (((2 * j + bSel) ^ lxor) << 4);
                ldsm4(u0, u1, u2, u3, addr);
                float v0 = __uint_as_float(u0), v1 = __uint_as_float(u1);
                float v2 = __uint_as_float(u2), v3 = __uint_as_float(u3);
                mma_tf32(acc[0][2 * ndp],     sc[0][j], v0, v1);
                mma_tf32(acc[1][2 * ndp],     sc[1][j], v0, v1);
                mma_tf32(acc[0][2 * ndp + 1], sc[0][j], v2, v3);
                mma_tf32(acc[1][2 * ndp + 1], sc[1][j], v2, v3);
            }
        }
        __syncthreads();
    }

    // ---- epilogue: normalize + tf32-round + store plain layout ----
    #pragma unroll
    for (int mi = 0; mi < 2; mi++) {
        float inv0 = 1.f / l_sum[mi][0];
        float inv1 = 1.f / l_sum[mi][1];
        float* ob = g_attn +
            ((size_t)b * LL + (size_t)ltile * 128 + warp * 32 + mi * 16) * EE + h * HD;
        #pragma unroll
        for (int nd = 0; nd < 8; nd++) {
            int col = nd * 8 + 2 * t;
            *reinterpret_cast<float2*>(ob + (size_t)g * EE + col) =
                make_float2(f2tf(acc[mi][nd][0] * inv0), f2tf(acc[mi][nd][1] * inv0));
            *reinterpret_cast<float2*>(ob + (size_t)(g + 8) * EE + col) =
                make_float2(f2tf(acc[mi][nd][2] * inv1), f2tf(acc[mi][nd][3] * inv1));
        }
    }
}

// ---- Kernel 2: projection GEMM, M=16384, N=1024 (W1||W2), K=512 ---------------
// 256 thr / 8 warps (4m x 2n), block 128m x 128n, warp 32m x 64n, k-tile 32.
// smem floats: sA[2] 128x32 @0 ; sB[2] 128x32 @8192
#define PROJ_SMEM (16384 * 4)

__global__ void __launch_bounds__(256, 2)
proj_kernel(const float* __restrict__ w1, const float* __restrict__ bias1,
            const float* __restrict__ w2, const float* __restrict__ bias2,
            float* __restrict__ out)
{
    extern __shared__ float smem[];
    const uint32_t sb  = (uint32_t)__cvta_generic_to_shared(smem);
    const uint32_t sA0 = sb;
    const uint32_t sB0 = sb + 8192 * 4;

    const int tid  = threadIdx.x;
    const int warp = tid >> 5;
    const int lane = tid & 31;
    const int g = lane >> 2, t = lane & 3;
    const int warpm = warp >> 1, warpn = warp & 1;
    const int lxor = lane & 7;
    const int aRow = lane & 15, aSel = lane >> 4;
    const int bRow = ((lane >> 4) << 3) + (lane & 7);
    const int bSel = (lane >> 3) & 1;

    const int mt = blockIdx.x;   // 0..127
    const int nt = blockIdx.y;   // 0..7 ; 0-3 -> W1, 4-7 -> W2

    const float* ag = g_attn + (size_t)mt * 128 * EE;
    const float* wg = (nt < 4) ? (w1 + (size_t)nt * 128 * EE)
                               : (w2 + (size_t)(nt - 4) * 128 * EE);

    // stage k-tile 0
    #pragma unroll
    for (int j = 0; j < 4; j++) {
        int i = tid + j * 256;
        int r = i >> 3, c = i & 7;
        uint32_t soff = (r << 7) + ((c ^ (r & 7)) << 4);
        cp16(sA0 + soff, ag + (size_t)r * EE + c * 4);
        cp16(sB0 + soff, wg + (size_t)r * EE + c * 4);
    }
    cp_commit();

    float acc[2][8][4];
    #pragma unroll
    for (int mi = 0; mi < 2; mi++)
        #pragma unroll
        for (int ni = 0; ni < 8; ni++)
            #pragma unroll
            for (int i = 0; i < 4; i++) acc[mi][ni][i] = 0.f;

    #pragma unroll 1
    for (int kt = 0; kt < 16; kt++) {
        const uint32_t sAb = sA0 + (kt & 1) * 4096 * 4;
        const uint32_t sBb = sB0 + (kt & 1) * 4096 * 4;

        if (kt + 1 < 16) {
            const uint32_t sAn = sA0 + ((kt + 1) & 1) * 4096 * 4;
            const uint32_t sBn = sB0 + ((kt + 1) & 1) * 4096 * 4;
            const float* agn = ag + (kt + 1) * 32;
            const float* wgn = wg + (kt + 1) * 32;
            #pragma unroll
            for (int j = 0; j < 4; j++) {
                int i = tid + j * 256;
                int r = i >> 3, c = i & 7;
                uint32_t soff = (r << 7) + ((c ^ (r & 7)) << 4);
                cp16(sAn + soff, agn + (size_t)r * EE + c * 4);
                cp16(sBn + soff, wgn + (size_t)r * EE + c * 4);
            }
            cp_commit();
            cp_wait<1>();
        } else {
            cp_wait<0>();
        }
        __syncthreads();

        #pragma unroll
        for (int ki = 0; ki < 4; ki++) {
            float af[2][4];
            #pragma unroll
            for (int mi = 0; mi < 2; mi++) {
                int r = warpm * 32 + mi * 16 + aRow;
                uint32_t addr = sAb + (r << 7) + (((2 * ki + aSel) ^ lxor) << 4);
                uint32_t u0, u1, u2, u3;
                ldsm4(u0, u1, u2, u3, addr);
                // g_attn already tf32-rounded: use raw
                af[mi][0] = __uint_as_float(u0);
                af[mi][1] = __uint_as_float(u1);
                af[mi][2] = __uint_as_float(u2);
                af[mi][3] = __uint_as_float(u3);
            }
            #pragma unroll
            for (int nip = 0; nip < 4; nip++) {
                uint32_t u0, u1, u2, u3;
                int r = warpn * 64 + nip * 16 + bRow;
                uint32_t addr = sBb + (r << 7) + (((2 * ki + bSel) ^ lxor) << 4);
                ldsm4(u0, u1, u2, u3, addr);
                float b0 = f2tf(__uint_as_float(u0));
                float b1 = f2tf(__uint_as_float(u1));
                float b2 = f2tf(__uint_as_float(u2));
                float b3 = f2tf(__uint_as_float(u3));
                mma_tf32(acc[0][2 * nip],     af[0], b0, b1);
                mma_tf32(acc[1][2 * nip],     af[1], b0, b1);
                mma_tf32(acc[0][2 * nip + 1], af[0], b2, b3);
                mma_tf32(acc[1][2 * nip + 1], af[1], b2, b3);
            }
        }
        __syncthreads();
    }

    // ---- epilogue: bias + store ----
    const float* bias = (nt < 4) ? bias1 : bias2;
    const int col0 = ((nt & 3) * 128) + warpn * 64;
    float* o = out + ((nt < 4) ? 0 : (size_t)BB * LL * EE)
             + ((size_t)mt * 128 + warpm * 32) * EE + col0;
    #pragma unroll
    for (int ni = 0; ni < 8; ni++) {
        int col = ni * 8 + 2 * t;
        float ba = __ldg(bias + col0 + col);
        float bb = __ldg(bias + col0 + col + 1);
        #pragma unroll
        for (int mi = 0; mi < 2; mi++) {
            size_t roff = (size_t)(mi * 16) * EE;
            *reinterpret_cast<float2*>(o + roff + (size_t)g * EE + col) =
                make_float2(acc[mi][ni][0] + ba, acc[mi][ni][1] + bb);
            *reinterpret_cast<float2*>(o + roff + (size_t)(g + 8) * EE + col) =
                make_float2(acc[mi][ni][2] + ba, acc[mi][ni][3] + bb);
        }
    }
}

// ---- launch -------------------------------------------------------------------

extern "C" void kernel_launch(void* const* d_in, const int* in_sizes, int n_in,
                              void* d_out, int out_size) {
    (void)in_sizes; (void)n_in; (void)out_size;
    const float* q  = (const float*)d_in[0];
    const float* k  = (const float*)d_in[1];
    const float* v  = (const float*)d_in[2];
    const float* w1 = (const float*)d_in[3];
    const float* b1 = (const float*)d_in[4];
    const float* w2 = (const float*)d_in[5];
    const float* b2 = (const float*)d_in[6];
    float* out = (float*)d_out;

    cudaFuncSetAttribute((const void*)attn_kernel,
                         cudaFuncAttributeMaxDynamicSharedMemorySize, ATTN_SMEM);
    cudaFuncSetAttribute((const void*)proj_kernel,
                         cudaFuncAttributeMaxDynamicSharedMemorySize, PROJ_SMEM);

    dim3 gv(16, 128);
    conv_v<<<gv, 256>>>(v);

    dim3 g1(LL / 128, HH, BB);            // (8, 8, 16)
    attn_kernel<<<g1, 128, ATTN_SMEM>>>(q, k);

    dim3 g2((BB * LL) / 128, 8);          // (128, 8)
    proj_kernel<<<g2, 256, PROJ_SMEM>>>(w1, b1, w2, b2, out);
}